// round 2
// baseline (speedup 1.0000x reference)
#include <cuda_runtime.h>
#include <cuda_bf16.h>

// Problem constants
#define SS   512
#define BB   256
#define DIN  202
#define HH   100
#define TT   19
#define MM   (SS*BB)   // 131072

// ---------------- scratch (device globals; no allocations allowed) ----------
__device__ float g_xp[2ll * SS * BB * HH];     // input projections, both dirs
__device__ float g_h [2ll * SS * BB * HH];     // hidden states, both dirs
__device__ float g_probs[(long long)SS * BB * TT]; // softmax emissions
__device__ float g_res[SS];                    // per-sequence CRF llh

// ---------------------------------------------------------------------------
// K1: input projection  xp[dir][s][b][j] = sum_i x[s][b][i]*W[j][i] + bih[j]+bhh[j]
// Tile: 128 rows of M x 100 cols per CTA. W (100x202) + x tile in dynamic SMEM.
// thread blocking: 2 rows x 25 cols.
// ---------------------------------------------------------------------------
__global__ void proj_kernel(const float* __restrict__ x,
                            const float* __restrict__ Wf,
                            const float* __restrict__ Wb,
                            const float* __restrict__ bihf,
                            const float* __restrict__ bhhf,
                            const float* __restrict__ bihb,
                            const float* __restrict__ bhhb)
{
    extern __shared__ __align__(16) float sm[];
    float* Ws = sm;              // [100][204]
    float* xs = sm + 100 * 204;  // [128][204]

    const int dir = blockIdx.y;
    const float* W  = dir ? Wb   : Wf;
    const float* bi = dir ? bihb : bihf;
    const float* bh = dir ? bhhb : bhhf;

    const int tid = threadIdx.x;
    const int r0  = blockIdx.x * 128;

    // load W (coalesced), padded stride 204
    for (int idx = tid; idx < 100 * DIN; idx += 256) {
        int j = idx / DIN, i = idx - j * DIN;
        Ws[j * 204 + i] = W[idx];
    }
    if (tid < 100) { Ws[tid * 204 + 202] = 0.f; Ws[tid * 204 + 203] = 0.f; }

    // load x tile
    for (int idx = tid; idx < 128 * DIN; idx += 256) {
        int r = idx / DIN, i = idx - r * DIN;
        xs[r * 204 + i] = x[(size_t)(r0 + r) * DIN + i];
    }
    if (tid < 128) { xs[tid * 204 + 202] = 0.f; xs[tid * 204 + 203] = 0.f; }
    __syncthreads();

    const int rg = tid & 63;        // 64 row-groups (2 rows each)
    const int cg = tid >> 6;        // 4 col-groups (25 cols each)
    const int ra = rg * 2;
    const int j0 = cg * 25;

    float acc0[25], acc1[25];
#pragma unroll
    for (int jj = 0; jj < 25; jj++) { acc0[jj] = 0.f; acc1[jj] = 0.f; }

    const float4* xa4 = (const float4*)&xs[ ra      * 204];
    const float4* xb4 = (const float4*)&xs[(ra + 1) * 204];

    for (int ii = 0; ii < 51; ii++) {
        float4 xa = xa4[ii];
        float4 xb = xb4[ii];
#pragma unroll
        for (int jj = 0; jj < 25; jj++) {
            float4 w = *(const float4*)&Ws[(j0 + jj) * 204 + ii * 4];
            float a = acc0[jj], b = acc1[jj];
            a = fmaf(xa.x, w.x, a); a = fmaf(xa.y, w.y, a);
            a = fmaf(xa.z, w.z, a); a = fmaf(xa.w, w.w, a);
            b = fmaf(xb.x, w.x, b); b = fmaf(xb.y, w.y, b);
            b = fmaf(xb.z, w.z, b); b = fmaf(xb.w, w.w, b);
            acc0[jj] = a; acc1[jj] = b;
        }
    }

#pragma unroll
    for (int jj = 0; jj < 25; jj++) {
        int j = j0 + jj;
        float bias = bi[j] + bh[j];
        size_t o = ((size_t)dir * MM + (r0 + ra)) * HH + j;
        g_xp[o]       = acc0[jj] + bias;
        g_xp[o + HH]  = acc1[jj] + bias;   // row ra+1
    }
}

// ---------------------------------------------------------------------------
// K2: recurrent scan. One CTA per (batch b, dir). 512 independent scans.
// h_t[j] = tanh(xp_t[j] + sum_i h_{t-1}[i] * Whh[j][i])
// W_hh in SMEM [j][i], h double-buffered, 1 __syncthreads per step.
// ---------------------------------------------------------------------------
__global__ void rnn_scan_kernel(const float* __restrict__ Whf,
                                const float* __restrict__ Whb)
{
    __shared__ __align__(16) float Wsh[HH * HH];
    __shared__ __align__(16) float hbuf[2][104];

    const int dir = blockIdx.y;
    const int b   = blockIdx.x;
    const float* Whh = dir ? Whb : Whf;
    const int tid = threadIdx.x;

    for (int idx = tid; idx < HH * HH; idx += 128) Wsh[idx] = Whh[idx];
    if (tid < 104) { hbuf[0][tid] = 0.f; hbuf[1][tid] = 0.f; }
    __syncthreads();

    const int  j   = tid;
    const bool act = (j < HH);
    const float4* Wrow = (const float4*)&Wsh[act ? j * HH : 0];

    // prefetch xp for first step
    int s0 = dir ? (SS - 1) : 0;
    float xv = 0.f;
    if (act) xv = g_xp[(((size_t)dir * SS + s0) * BB + b) * HH + j];

    for (int t = 0; t < SS; t++) {
        int s = dir ? (SS - 1 - t) : t;

        // prefetch next step's xp
        float xnext = 0.f;
        if (t + 1 < SS) {
            int sn = dir ? (SS - 2 - t) : (t + 1);
            if (act) xnext = g_xp[(((size_t)dir * SS + sn) * BB + b) * HH + j];
        }

        const float* hc = hbuf[t & 1];
        float a0 = 0.f, a1 = 0.f, a2 = 0.f, a3 = 0.f;
        if (act) {
#pragma unroll
            for (int ii = 0; ii < 25; ii++) {
                float4 h4 = *(const float4*)&hc[ii * 4];
                float4 w4 = Wrow[ii];
                a0 = fmaf(h4.x, w4.x, a0);
                a1 = fmaf(h4.y, w4.y, a1);
                a2 = fmaf(h4.z, w4.z, a2);
                a3 = fmaf(h4.w, w4.w, a3);
            }
            float z = xv + ((a0 + a1) + (a2 + a3));
            float hn;
            asm("tanh.approx.f32 %0, %1;" : "=f"(hn) : "f"(z));
            hbuf[(t + 1) & 1][j] = hn;
            g_h[(((size_t)dir * SS + s) * BB + b) * HH + j] = hn;
        }
        xv = xnext;
        __syncthreads();
    }
}

// ---------------------------------------------------------------------------
// K3: logits + softmax fused.
// ---------------------------------------------------------------------------
__global__ void logits_softmax_kernel(const float* __restrict__ Wtag,
                                      const float* __restrict__ btag)
{
    extern __shared__ __align__(16) float sm[];
    float* Wt = sm;           // [200][19]  (3800 floats)
    float* hs = sm + 3800;    // [128][201]

    const int tid  = threadIdx.x;
    const int row0 = blockIdx.x * 128;

    for (int idx = tid; idx < TT * 200; idx += 128) {
        int t = idx / 200, i = idx - t * 200;
        Wt[i * TT + t] = Wtag[idx];
    }
    const float* hf = g_h;
    const float* hb = g_h + (size_t)SS * BB * HH;
    for (int idx = tid; idx < 128 * HH; idx += 128) {
        int r = idx / HH, i = idx - r * HH;
        hs[r * 201 + i]       = hf[(size_t)(row0 + r) * HH + i];
        hs[r * 201 + 100 + i] = hb[(size_t)(row0 + r) * HH + i];
    }
    __syncthreads();

    float acc[TT];
#pragma unroll
    for (int t = 0; t < TT; t++) acc[t] = btag[t];

    const float* hrow = &hs[tid * 201];
    for (int i = 0; i < 200; i++) {
        float hv = hrow[i];
#pragma unroll
        for (int t = 0; t < TT; t++)
            acc[t] = fmaf(hv, Wt[i * TT + t], acc[t]);
    }

    // softmax over TT
    float m = acc[0];
#pragma unroll
    for (int t = 1; t < TT; t++) m = fmaxf(m, acc[t]);
    float sum = 0.f;
#pragma unroll
    for (int t = 0; t < TT; t++) { acc[t] = __expf(acc[t] - m); sum += acc[t]; }
    float inv = 1.0f / sum;

    size_t o = (size_t)(row0 + tid) * TT;
#pragma unroll
    for (int t = 0; t < TT; t++) g_probs[o + t] = acc[t] * inv;
}

// ---------------------------------------------------------------------------
// K4: CRF log-likelihood. One warp per sequence n (N=S=512, L=B=256, T=19).
// y is INT32 (JAX downgrades int64 without x64 mode).
// ---------------------------------------------------------------------------
__global__ void crf_kernel(const int* __restrict__ y,
                           const float* __restrict__ start_tr,
                           const float* __restrict__ end_tr,
                           const float* __restrict__ trans)
{
    __shared__ float trans_sh[TT * TT];
    __shared__ float p_sh[8][32];

    const int tid = threadIdx.x;
    for (int idx = tid; idx < TT * TT; idx += 256) trans_sh[idx] = trans[idx];
    __syncthreads();

    const int wid = tid >> 5;
    const int k   = tid & 31;
    const int n   = blockIdx.x * 8 + wid;
    const bool lk = (k < TT);
    const unsigned FULL = 0xffffffffu;

    float E[TT];
#pragma unroll
    for (int jj = 0; jj < TT; jj++)
        E[jj] = lk ? __expf(trans_sh[jj * TT + k]) : 0.f;

    const float* em_base = g_probs + (size_t)n * BB * TT;
    const int*   yrow    = y + (size_t)n * BB;

    float em    = lk ? em_base[k] : 0.f;
    float alpha = lk ? (start_tr[k] + em) : -1e30f;

    int   ytag = yrow[0];
    float num  = start_tr[ytag] + __shfl_sync(FULL, em, ytag);
    int   yprev = ytag;

    for (int l = 1; l < BB; l++) {
        float emn = lk ? em_base[l * TT + k] : 0.f;   // issue loads early
        int   yt  = yrow[l];

        float a0 = __shfl_sync(FULL, alpha, 0);
        float p  = __expf(alpha - a0);                // k>=19 -> 0
        p_sh[wid][k] = p;
        __syncwarp();

        float ssum = 0.f;
#pragma unroll
        for (int jj = 0; jj < TT; jj++)
            ssum = fmaf(p_sh[wid][jj], E[jj], ssum);
        __syncwarp();

        alpha = lk ? (emn + a0 + __logf(ssum)) : -1e30f;

        num += trans_sh[yprev * TT + yt];
        num += __shfl_sync(FULL, emn, yt);
        yprev = yt;
    }

    // denominator: logsumexp(alpha + end_tr)
    float av = lk ? (alpha + end_tr[k]) : -1e30f;
    float m = av;
#pragma unroll
    for (int off = 16; off; off >>= 1)
        m = fmaxf(m, __shfl_xor_sync(FULL, m, off));
    float e = __expf(av - m);
#pragma unroll
    for (int off = 16; off; off >>= 1)
        e += __shfl_xor_sync(FULL, e, off);
    float den = m + __logf(e);

    num += end_tr[yprev];
    if (k == 0) g_res[n] = num - den;
}

// ---------------------------------------------------------------------------
// K5: deterministic final reduce of 512 per-sequence results -> scalar
// ---------------------------------------------------------------------------
__global__ void reduce_kernel(float* __restrict__ out)
{
    __shared__ float buf[512];
    int tid = threadIdx.x;
    buf[tid] = g_res[tid];
    __syncthreads();
    for (int s = 256; s > 0; s >>= 1) {
        if (tid < s) buf[tid] += buf[tid + s];
        __syncthreads();
    }
    if (tid == 0) out[0] = buf[0];
}

// ---------------------------------------------------------------------------
extern "C" void kernel_launch(void* const* d_in, const int* in_sizes, int n_in,
                              void* d_out, int out_size)
{
    const float* x        = (const float*)d_in[0];
    const int*   y        = (const int*)d_in[1];      // int32 (JAX default)
    const float* W_ih_f   = (const float*)d_in[2];
    const float* W_hh_f   = (const float*)d_in[3];
    const float* b_ih_f   = (const float*)d_in[4];
    const float* b_hh_f   = (const float*)d_in[5];
    const float* W_ih_b   = (const float*)d_in[6];
    const float* W_hh_b   = (const float*)d_in[7];
    const float* b_ih_b   = (const float*)d_in[8];
    const float* b_hh_b   = (const float*)d_in[9];
    const float* W_tag    = (const float*)d_in[10];
    const float* b_tag    = (const float*)d_in[11];
    const float* start_tr = (const float*)d_in[12];
    const float* end_tr   = (const float*)d_in[13];
    const float* trans    = (const float*)d_in[14];
    float*       out      = (float*)d_out;

    const int proj_smem   = (100 * 204 + 128 * 204) * 4;        // 186048 B
    const int logits_smem = (3800 + 128 * 201) * 4;             // 118112 B
    cudaFuncSetAttribute(proj_kernel,
                         cudaFuncAttributeMaxDynamicSharedMemorySize, proj_smem);
    cudaFuncSetAttribute(logits_softmax_kernel,
                         cudaFuncAttributeMaxDynamicSharedMemorySize, logits_smem);

    proj_kernel<<<dim3(MM / 128, 2), 256, proj_smem>>>(
        x, W_ih_f, W_ih_b, b_ih_f, b_hh_f, b_ih_b, b_hh_b);

    rnn_scan_kernel<<<dim3(BB, 2), 128>>>(W_hh_f, W_hh_b);

    logits_softmax_kernel<<<MM / 128, 128, logits_smem>>>(W_tag, b_tag);

    crf_kernel<<<SS / 8, 256>>>(y, start_tr, end_tr, trans);

    reduce_kernel<<<1, 512>>>(out);
}

// round 3
// speedup vs baseline: 1.3690x; 1.3690x over previous
#include <cuda_runtime.h>
#include <cuda_bf16.h>

// Problem constants
#define SS   512
#define BB   256
#define DIN  202
#define HH   100
#define TT   19
#define MM   (SS*BB)   // 131072

// ---------------- scratch (device globals; no allocations allowed) ----------
__device__ float g_xp[2ll * SS * BB * HH];     // input projections, both dirs
__device__ float g_h [2ll * SS * BB * HH];     // hidden states, both dirs
__device__ float g_probs[(long long)SS * BB * TT]; // softmax emissions
__device__ float g_res[SS];                    // per-sequence CRF llh

// ---------------- packed f32x2 helpers (FFMA2: ptxas won't emit from C++) ----
typedef unsigned long long u64;

__device__ __forceinline__ u64 pk2(float lo, float hi) {
    u64 r; asm("mov.b64 %0, {%1,%2};" : "=l"(r) : "f"(lo), "f"(hi)); return r;
}
__device__ __forceinline__ float2 upk2(u64 v) {
    float2 f; asm("mov.b64 {%0,%1}, %2;" : "=f"(f.x), "=f"(f.y) : "l"(v)); return f;
}
__device__ __forceinline__ void ffma2(u64& d, u64 a, u64 b) {
    asm("fma.rn.f32x2 %0, %1, %2, %3;" : "=l"(d) : "l"(a), "l"(b), "l"(d));
}

// ---------------------------------------------------------------------------
// K1: input projection  xp[dir][s][b][j] = sum_i x[s][b][i]*W[j][i] + bih[j]+bhh[j]
// 128 rows x 100 cols per CTA; W + x tile in SMEM; 2 rows x 25 cols per thread.
// Inner product vectorized with fma.rn.f32x2 (pairs along i).
// ---------------------------------------------------------------------------
__global__ void __launch_bounds__(256)
proj_kernel(const float* __restrict__ x,
            const float* __restrict__ Wf,
            const float* __restrict__ Wb,
            const float* __restrict__ bihf,
            const float* __restrict__ bhhf,
            const float* __restrict__ bihb,
            const float* __restrict__ bhhb)
{
    extern __shared__ __align__(16) float sm[];
    float* Ws = sm;              // [100][204]
    float* xs = sm + 100 * 204;  // [128][204]

    const int dir = blockIdx.y;
    const float* W  = dir ? Wb   : Wf;
    const float* bi = dir ? bihb : bihf;
    const float* bh = dir ? bhhb : bhhf;

    const int tid = threadIdx.x;
    const int r0  = blockIdx.x * 128;

    for (int idx = tid; idx < 100 * DIN; idx += 256) {
        int j = idx / DIN, i = idx - j * DIN;
        Ws[j * 204 + i] = W[idx];
    }
    if (tid < 100) { Ws[tid * 204 + 202] = 0.f; Ws[tid * 204 + 203] = 0.f; }

    for (int idx = tid; idx < 128 * DIN; idx += 256) {
        int r = idx / DIN, i = idx - r * DIN;
        xs[r * 204 + i] = x[(size_t)(r0 + r) * DIN + i];
    }
    if (tid < 128) { xs[tid * 204 + 202] = 0.f; xs[tid * 204 + 203] = 0.f; }
    __syncthreads();

    const int rg = tid & 63;        // 64 row-groups (2 rows each)
    const int cg = tid >> 6;        // 4 col-groups (25 cols each)
    const int ra = rg * 2;
    const int j0 = cg * 25;

    u64 acc0[25], acc1[25];
#pragma unroll
    for (int jj = 0; jj < 25; jj++) { acc0[jj] = 0ull; acc1[jj] = 0ull; }

    const ulonglong2* xa8 = (const ulonglong2*)&xs[ ra      * 204];
    const ulonglong2* xb8 = (const ulonglong2*)&xs[(ra + 1) * 204];

    for (int ii = 0; ii < 51; ii++) {
        ulonglong2 xa = xa8[ii];
        ulonglong2 xb = xb8[ii];
#pragma unroll
        for (int jj = 0; jj < 25; jj++) {
            ulonglong2 w = *(const ulonglong2*)&Ws[(j0 + jj) * 204 + ii * 4];
            ffma2(acc0[jj], xa.x, w.x);
            ffma2(acc0[jj], xa.y, w.y);
            ffma2(acc1[jj], xb.x, w.x);
            ffma2(acc1[jj], xb.y, w.y);
        }
    }

#pragma unroll
    for (int jj = 0; jj < 25; jj++) {
        int j = j0 + jj;
        float bias = bi[j] + bh[j];
        float2 a = upk2(acc0[jj]);
        float2 b = upk2(acc1[jj]);
        size_t o = ((size_t)dir * MM + (r0 + ra)) * HH + j;
        g_xp[o]      = a.x + a.y + bias;
        g_xp[o + HH] = b.x + b.y + bias;
    }
}

// ---------------------------------------------------------------------------
// K2: recurrent scan. One CTA per batch b, BOTH dirs (threads 0-127 dir0,
// 128-255 dir1; j = tid&127, active j<100). Each thread's W_hh row lives in
// 50 packed u64 REGISTERS (loaded once) -> no per-step SMEM W traffic.
// h reads are warp-broadcast LDS. Per-dir named barriers (dirs independent).
// ---------------------------------------------------------------------------
__global__ void __launch_bounds__(256, 2)
rnn_scan_kernel(const float* __restrict__ Whf,
                const float* __restrict__ Whb)
{
    __shared__ __align__(16) float hbuf[2][2][104];   // [dir][parity][j]

    const int tid = threadIdx.x;
    const int dir = tid >> 7;
    const int j   = tid & 127;
    const int b   = blockIdx.x;
    const bool act = (j < 100);
    const int jc  = act ? j : 0;

    // preload W row into registers (25 x 16B loads, packed pairs)
    const float* Wrow = (dir ? Whb : Whf) + jc * HH;
    u64 Wp[50];
#pragma unroll
    for (int ii = 0; ii < 25; ii++) {
        ulonglong2 w = *(const ulonglong2*)&Wrow[ii * 4];
        Wp[2 * ii]     = w.x;
        Wp[2 * ii + 1] = w.y;
    }

    if (j < 104) { hbuf[dir][0][j] = 0.f; hbuf[dir][1][j] = 0.f; }
    __syncthreads();

    // prefetch xp for first step
    const int s0 = dir ? (SS - 1) : 0;
    float xv = act ? g_xp[(((size_t)dir * SS + s0) * BB + b) * HH + j] : 0.f;

    for (int t = 0; t < SS; t++) {
        int s = dir ? (SS - 1 - t) : t;

        float xnext = 0.f;
        if (t + 1 < SS && act) {
            int sn = dir ? (SS - 2 - t) : (t + 1);
            xnext = g_xp[(((size_t)dir * SS + sn) * BB + b) * HH + j];
        }

        const ulonglong2* hc = (const ulonglong2*)hbuf[dir][t & 1];
        u64 acc0 = 0ull, acc1 = 0ull;
#pragma unroll
        for (int ii = 0; ii < 25; ii++) {
            ulonglong2 h2 = hc[ii];                  // warp-broadcast
            ffma2(acc0, h2.x, Wp[2 * ii]);
            ffma2(acc1, h2.y, Wp[2 * ii + 1]);
        }
        float2 a = upk2(acc0);
        float2 c = upk2(acc1);
        float z = xv + ((a.x + a.y) + (c.x + c.y));
        float hn;
        asm("tanh.approx.f32 %0, %1;" : "=f"(hn) : "f"(z));
        if (act) {
            hbuf[dir][(t + 1) & 1][j] = hn;
            g_h[(((size_t)dir * SS + s) * BB + b) * HH + j] = hn;
        }
        xv = xnext;
        // per-direction barrier (128 threads each); ids 1 & 2
        asm volatile("bar.sync %0, 128;" :: "r"(dir + 1) : "memory");
    }
}

// ---------------------------------------------------------------------------
// K3: logits + softmax fused (f32x2 inner product, pairs along i).
// hs stride 202 (8B aligned rows for float2 loads); Wt2 packed pairs [i2][t].
// ---------------------------------------------------------------------------
__global__ void __launch_bounds__(128)
logits_softmax_kernel(const float* __restrict__ Wtag,
                      const float* __restrict__ btag)
{
    extern __shared__ __align__(16) float sm[];
    float* Wt2f = sm;           // float2[100][19] -> 3800 floats
    float* hs   = sm + 3800;    // [128][202]

    const int tid  = threadIdx.x;
    const int row0 = blockIdx.x * 128;

    for (int idx = tid; idx < TT * 100; idx += 128) {
        int t = idx / 100, i2 = idx - t * 100;
        Wt2f[(i2 * TT + t) * 2]     = Wtag[t * 200 + 2 * i2];
        Wt2f[(i2 * TT + t) * 2 + 1] = Wtag[t * 200 + 2 * i2 + 1];
    }
    const float* hf = g_h;
    const float* hb = g_h + (size_t)SS * BB * HH;
    for (int idx = tid; idx < 128 * HH; idx += 128) {
        int r = idx / HH, i = idx - r * HH;
        hs[r * 202 + i]       = hf[(size_t)(row0 + r) * HH + i];
        hs[r * 202 + 100 + i] = hb[(size_t)(row0 + r) * HH + i];
    }
    __syncthreads();

    u64 acc[TT];
#pragma unroll
    for (int t = 0; t < TT; t++) acc[t] = 0ull;

    const u64* h2 = (const u64*)&hs[tid * 202];
    for (int i2 = 0; i2 < 100; i2++) {
        u64 hp = h2[i2];
        const u64* wrow = (const u64*)&Wt2f[i2 * TT * 2];
#pragma unroll
        for (int t = 0; t < TT; t++)
            ffma2(acc[t], hp, wrow[t]);
    }

    float lg[TT];
#pragma unroll
    for (int t = 0; t < TT; t++) {
        float2 f = upk2(acc[t]);
        lg[t] = f.x + f.y + btag[t];
    }

    float m = lg[0];
#pragma unroll
    for (int t = 1; t < TT; t++) m = fmaxf(m, lg[t]);
    float sum = 0.f;
#pragma unroll
    for (int t = 0; t < TT; t++) { lg[t] = __expf(lg[t] - m); sum += lg[t]; }
    float inv = 1.0f / sum;

    size_t o = (size_t)(row0 + tid) * TT;
#pragma unroll
    for (int t = 0; t < TT; t++) g_probs[o + t] = lg[t] * inv;
}

// ---------------------------------------------------------------------------
// K4: CRF log-likelihood. ONE WARP PER SEQUENCE, 512 CTAs of 32 threads.
// Numerator computed in parallel across lanes (hoisted out of the scan).
// Forward recursion: rescale-by-lane0 linear mat-vec with E=exp(trans) in
// registers; ssum via 4-way tree.
// ---------------------------------------------------------------------------
__global__ void __launch_bounds__(32)
crf_kernel(const int* __restrict__ y,
           const float* __restrict__ start_tr,
           const float* __restrict__ end_tr,
           const float* __restrict__ trans)
{
    __shared__ float trans_sh[TT * TT];
    __shared__ float p_sh[32];

    const int k = threadIdx.x;
    const int n = blockIdx.x;
    const bool lk = (k < TT);
    const unsigned FULL = 0xffffffffu;

    for (int idx = k; idx < TT * TT; idx += 32) trans_sh[idx] = trans[idx];
    __syncwarp();

    float E[TT];
#pragma unroll
    for (int jj = 0; jj < TT; jj++)
        E[jj] = lk ? __expf(trans_sh[jj * TT + k]) : 0.f;

    const float* em_base = g_probs + (size_t)n * BB * TT;
    const int*   yrow    = y + (size_t)n * BB;

    // ---- numerator: fully parallel over positions l ----
    float npart = 0.f;
    for (int l = k; l < BB; l += 32) {
        int yl = yrow[l];
        npart += em_base[l * TT + yl];
        if (l + 1 < BB) npart += trans_sh[yl * TT + yrow[l + 1]];
    }
    if (k == 0) npart += start_tr[yrow[0]] + end_tr[yrow[BB - 1]];
#pragma unroll
    for (int off = 16; off; off >>= 1)
        npart += __shfl_xor_sync(FULL, npart, off);
    const float num = npart;    // same on all lanes

    // ---- forward recursion (log partition) ----
    float alpha = lk ? (start_tr[k] + em_base[k]) : -1e30f;

    float em_nxt = lk ? em_base[1 * TT + k] : 0.f;   // prefetch for l=1
    for (int l = 1; l < BB; l++) {
        float em_pf = 0.f;
        if (l + 1 < BB && lk) em_pf = em_base[(l + 1) * TT + k];  // next iter

        float a0 = __shfl_sync(FULL, alpha, 0);
        float p  = __expf(alpha - a0);               // k>=19 -> ~0
        p_sh[k] = p;
        __syncwarp();

        float s0 = 0.f, s1 = 0.f, s2 = 0.f, s3 = 0.f;
#pragma unroll
        for (int jj = 0; jj < 5; jj++)  s0 = fmaf(p_sh[jj],      E[jj],      s0);
#pragma unroll
        for (int jj = 0; jj < 5; jj++)  s1 = fmaf(p_sh[5 + jj],  E[5 + jj],  s1);
#pragma unroll
        for (int jj = 0; jj < 5; jj++)  s2 = fmaf(p_sh[10 + jj], E[10 + jj], s2);
#pragma unroll
        for (int jj = 0; jj < 4; jj++)  s3 = fmaf(p_sh[15 + jj], E[15 + jj], s3);
        float ssum = (s0 + s1) + (s2 + s3);
        __syncwarp();

        alpha = lk ? (em_nxt + a0 + __logf(ssum)) : -1e30f;
        em_nxt = em_pf;
    }

    float av = lk ? (alpha + end_tr[k]) : -1e30f;
    float m = av;
#pragma unroll
    for (int off = 16; off; off >>= 1)
        m = fmaxf(m, __shfl_xor_sync(FULL, m, off));
    float e = __expf(av - m);
#pragma unroll
    for (int off = 16; off; off >>= 1)
        e += __shfl_xor_sync(FULL, e, off);
    float den = m + __logf(e);

    if (k == 0) g_res[n] = num - den;
}

// ---------------------------------------------------------------------------
// K5: deterministic final reduce of 512 per-sequence results -> scalar
// ---------------------------------------------------------------------------
__global__ void reduce_kernel(float* __restrict__ out)
{
    __shared__ float buf[512];
    int tid = threadIdx.x;
    buf[tid] = g_res[tid];
    __syncthreads();
    for (int s = 256; s > 0; s >>= 1) {
        if (tid < s) buf[tid] += buf[tid + s];
        __syncthreads();
    }
    if (tid == 0) out[0] = buf[0];
}

// ---------------------------------------------------------------------------
extern "C" void kernel_launch(void* const* d_in, const int* in_sizes, int n_in,
                              void* d_out, int out_size)
{
    const float* x        = (const float*)d_in[0];
    const int*   y        = (const int*)d_in[1];      // int32 (JAX default)
    const float* W_ih_f   = (const float*)d_in[2];
    const float* W_hh_f   = (const float*)d_in[3];
    const float* b_ih_f   = (const float*)d_in[4];
    const float* b_hh_f   = (const float*)d_in[5];
    const float* W_ih_b   = (const float*)d_in[6];
    const float* W_hh_b   = (const float*)d_in[7];
    const float* b_ih_b   = (const float*)d_in[8];
    const float* b_hh_b   = (const float*)d_in[9];
    const float* W_tag    = (const float*)d_in[10];
    const float* b_tag    = (const float*)d_in[11];
    const float* start_tr = (const float*)d_in[12];
    const float* end_tr   = (const float*)d_in[13];
    const float* trans    = (const float*)d_in[14];
    float*       out      = (float*)d_out;

    const int proj_smem   = (100 * 204 + 128 * 204) * 4;        // 186048 B
    const int logits_smem = (3800 + 128 * 202) * 4;             // 118624 B
    cudaFuncSetAttribute(proj_kernel,
                         cudaFuncAttributeMaxDynamicSharedMemorySize, proj_smem);
    cudaFuncSetAttribute(logits_softmax_kernel,
                         cudaFuncAttributeMaxDynamicSharedMemorySize, logits_smem);

    proj_kernel<<<dim3(MM / 128, 2), 256, proj_smem>>>(
        x, W_ih_f, W_ih_b, b_ih_f, b_hh_f, b_ih_b, b_hh_b);

    rnn_scan_kernel<<<BB, 256>>>(W_hh_f, W_hh_b);

    logits_softmax_kernel<<<MM / 128, 128, logits_smem>>>(W_tag, b_tag);

    crf_kernel<<<SS, 32>>>(y, start_tr, end_tr, trans);

    reduce_kernel<<<1, 512>>>(out);
}